// round 1
// baseline (speedup 1.0000x reference)
#include <cuda_runtime.h>
#include <math.h>

// ---------------- problem constants (fixed shapes) ----------------
#define T_TOKENS 100352      // 8 * 112 * 112
#define C_DIM    256
#define HID      1024
#define QKV_DIM  768
#define HEADS    8
#define DH       32
#define IMG      112
#define WS7      7
#define NWROW    16          // 112/7
#define TOK_PER_IMG 12544    // 112*112

// ---------------- scratch (device globals; no allocs) ----------------
__device__ float g_ln  [(size_t)T_TOKENS * C_DIM];
__device__ float g_qkv [(size_t)T_TOKENS * QKV_DIM];
__device__ float g_attn[(size_t)T_TOKENS * C_DIM];
__device__ float g_x2  [(size_t)T_TOKENS * C_DIM];
__device__ float g_fc1 [(size_t)T_TOKENS * HID];

// ---------------- LayerNorm: warp per row (C=256 -> 8 floats/lane) ----------------
__global__ void ln_kernel(const float* __restrict__ x,
                          const float* __restrict__ gamma,
                          const float* __restrict__ beta,
                          float* __restrict__ out) {
    int row  = blockIdx.x * 8 + (threadIdx.x >> 5);
    int lane = threadIdx.x & 31;
    const float4* xr = (const float4*)(x + (size_t)row * C_DIM);
    float4 v0 = xr[lane];
    float4 v1 = xr[lane + 32];
    float s  = v0.x + v0.y + v0.z + v0.w + v1.x + v1.y + v1.z + v1.w;
    float s2 = v0.x*v0.x + v0.y*v0.y + v0.z*v0.z + v0.w*v0.w
             + v1.x*v1.x + v1.y*v1.y + v1.z*v1.z + v1.w*v1.w;
    #pragma unroll
    for (int o = 16; o > 0; o >>= 1) {
        s  += __shfl_xor_sync(0xffffffffu, s,  o);
        s2 += __shfl_xor_sync(0xffffffffu, s2, o);
    }
    float mean = s * (1.f / 256.f);
    float var  = s2 * (1.f / 256.f) - mean * mean;
    float inv  = rsqrtf(var + 1e-5f);

    const float4* gr = (const float4*)gamma;
    const float4* br = (const float4*)beta;
    float4 g0 = gr[lane], g1v = gr[lane + 32];
    float4 b0 = br[lane], b1v = br[lane + 32];
    float4 o0, o1;
    o0.x = (v0.x - mean) * inv * g0.x + b0.x;
    o0.y = (v0.y - mean) * inv * g0.y + b0.y;
    o0.z = (v0.z - mean) * inv * g0.z + b0.z;
    o0.w = (v0.w - mean) * inv * g0.w + b0.w;
    o1.x = (v1.x - mean) * inv * g1v.x + b1v.x;
    o1.y = (v1.y - mean) * inv * g1v.y + b1v.y;
    o1.z = (v1.z - mean) * inv * g1v.z + b1v.z;
    o1.w = (v1.w - mean) * inv * g1v.w + b1v.w;
    float4* orow = (float4*)(out + (size_t)row * C_DIM);
    orow[lane]      = o0;
    orow[lane + 32] = o1;
}

// ---------------- GEMM: C[M,N] = A[M,K] @ W[N,K]^T + bias (+epilogue) ----------------
// EPI: 0 = bias only, 1 = bias + residual, 2 = bias + exact GELU
template<int EPI>
__launch_bounds__(256, 2)
__global__ void gemm_kernel(const float* __restrict__ A,
                            const float* __restrict__ W,
                            const float* __restrict__ bias,
                            const float* __restrict__ res,
                            float* __restrict__ C,
                            int M, int N, int K) {
    __shared__ float As[8][128];
    __shared__ float Bs[8][128];
    int tid = threadIdx.x;
    int m0 = blockIdx.y * 128;
    int n0 = blockIdx.x * 128;
    int lrow = tid >> 1;
    int lseg = (tid & 1) * 4;
    int tx = tid & 15;   // N direction
    int ty = tid >> 4;   // M direction

    const float* Aptr = A + (size_t)(m0 + lrow) * K + lseg;
    const float* Wptr = W + (size_t)(n0 + lrow) * K + lseg;

    float acc[8][8];
    #pragma unroll
    for (int i = 0; i < 8; i++)
        #pragma unroll
        for (int j = 0; j < 8; j++) acc[i][j] = 0.f;

    for (int k0 = 0; k0 < K; k0 += 8) {
        float4 av = *(const float4*)(Aptr + k0);
        float4 wv = *(const float4*)(Wptr + k0);
        As[lseg + 0][lrow] = av.x;
        As[lseg + 1][lrow] = av.y;
        As[lseg + 2][lrow] = av.z;
        As[lseg + 3][lrow] = av.w;
        Bs[lseg + 0][lrow] = wv.x;
        Bs[lseg + 1][lrow] = wv.y;
        Bs[lseg + 2][lrow] = wv.z;
        Bs[lseg + 3][lrow] = wv.w;
        __syncthreads();
        #pragma unroll
        for (int kk = 0; kk < 8; kk++) {
            float4 a0 = *(const float4*)&As[kk][ty * 8];
            float4 a1 = *(const float4*)&As[kk][ty * 8 + 4];
            float4 b0 = *(const float4*)&Bs[kk][tx * 8];
            float4 b1 = *(const float4*)&Bs[kk][tx * 8 + 4];
            float a[8] = {a0.x, a0.y, a0.z, a0.w, a1.x, a1.y, a1.z, a1.w};
            float b[8] = {b0.x, b0.y, b0.z, b0.w, b1.x, b1.y, b1.z, b1.w};
            #pragma unroll
            for (int i = 0; i < 8; i++)
                #pragma unroll
                for (int j = 0; j < 8; j++)
                    acc[i][j] += a[i] * b[j];
        }
        __syncthreads();
    }

    // epilogue
    int nbase = n0 + tx * 8;
    float4 bv0 = *(const float4*)(bias + nbase);
    float4 bv1 = *(const float4*)(bias + nbase + 4);
    float bb[8] = {bv0.x, bv0.y, bv0.z, bv0.w, bv1.x, bv1.y, bv1.z, bv1.w};
    #pragma unroll
    for (int i = 0; i < 8; i++) {
        int m = m0 + ty * 8 + i;
        float v[8];
        #pragma unroll
        for (int j = 0; j < 8; j++) v[j] = acc[i][j] + bb[j];
        if (EPI == 1) {
            const float4* rr = (const float4*)(res + (size_t)m * N + nbase);
            float4 r0 = rr[0], r1 = rr[1];
            v[0] += r0.x; v[1] += r0.y; v[2] += r0.z; v[3] += r0.w;
            v[4] += r1.x; v[5] += r1.y; v[6] += r1.z; v[7] += r1.w;
        }
        if (EPI == 2) {
            #pragma unroll
            for (int j = 0; j < 8; j++)
                v[j] = 0.5f * v[j] * (1.f + erff(v[j] * 0.7071067811865476f));
        }
        float4* crow = (float4*)(C + (size_t)m * N + nbase);
        crow[0] = make_float4(v[0], v[1], v[2], v[3]);
        crow[1] = make_float4(v[4], v[5], v[6], v[7]);
    }
}

// ---------------- fused window attention (per window, per head) ----------------
// grid = 2048 windows * 8 heads; block = 64 threads (threads 0..48 own rows)
__global__ void attn_kernel(const float* __restrict__ qkv,
                            float* __restrict__ attn_out) {
    __shared__ float ks[49][32];
    __shared__ float vs[49][32];
    __shared__ float ss[49][56];   // padded row stride
    __shared__ int   tok[49];

    int head = blockIdx.x & 7;
    int win  = blockIdx.x >> 3;
    int n    = win >> 8;          // image index
    int wrem = win & 255;
    int wr   = wrem >> 4;
    int wc   = wrem & 15;
    int tid  = threadIdx.x;

    if (tid < 49) {
        int hh = wr * WS7 + tid / 7;
        int ww = wc * WS7 + tid % 7;
        tok[tid] = n * TOK_PER_IMG + hh * IMG + ww;
    }
    __syncthreads();

    int cb = head * DH;
    // load K and V tiles (gathered): 49 rows * 8 float4 each
    for (int i = tid; i < 49 * 8; i += 64) {
        int row = i >> 3;
        int c4  = (i & 7) * 4;
        const float* base = qkv + (size_t)tok[row] * QKV_DIM;
        *(float4*)&ks[row][c4] = *(const float4*)(base + C_DIM     + cb + c4);
        *(float4*)&vs[row][c4] = *(const float4*)(base + 2 * C_DIM + cb + c4);
    }
    __syncthreads();

    if (tid < 49) {
        float qr[32];
        const float* qb = qkv + (size_t)tok[tid] * QKV_DIM + cb;
        #pragma unroll
        for (int dd = 0; dd < 32; dd += 4) {
            float4 v = *(const float4*)(qb + dd);
            qr[dd] = v.x; qr[dd + 1] = v.y; qr[dd + 2] = v.z; qr[dd + 3] = v.w;
        }
        const float scale = 0.17677669529663687f;  // 1/sqrt(32)
        float mx = -1e30f;
        for (int m = 0; m < 49; m++) {
            float d = 0.f;
            #pragma unroll
            for (int dd = 0; dd < 32; dd++) d += qr[dd] * ks[m][dd];
            d *= scale;
            ss[tid][m] = d;
            mx = fmaxf(mx, d);
        }
        float sum = 0.f;
        for (int m = 0; m < 49; m++) {
            float e = __expf(ss[tid][m] - mx);
            ss[tid][m] = e;
            sum += e;
        }
        float inv = 1.f / sum;
        float out[32];
        #pragma unroll
        for (int dd = 0; dd < 32; dd++) out[dd] = 0.f;
        for (int m = 0; m < 49; m++) {
            float p = ss[tid][m];
            #pragma unroll
            for (int dd = 0; dd < 32; dd++) out[dd] += p * vs[m][dd];
        }
        float* ob = attn_out + (size_t)tok[tid] * C_DIM + cb;
        #pragma unroll
        for (int dd = 0; dd < 32; dd += 4) {
            *(float4*)(ob + dd) = make_float4(out[dd] * inv, out[dd + 1] * inv,
                                              out[dd + 2] * inv, out[dd + 3] * inv);
        }
    }
}

// ---------------- launch ----------------
extern "C" void kernel_launch(void* const* d_in, const int* in_sizes, int n_in,
                              void* d_out, int out_size) {
    // input order: x, H, W, g1, b1, w_qkv, b_qkv, w_proj, b_proj, g2, b2,
    //              w_fc1, b_fc1, w_fc2, b_fc2
    const float* x      = (const float*)d_in[0];
    const float* g1     = (const float*)d_in[3];
    const float* b1     = (const float*)d_in[4];
    const float* w_qkv  = (const float*)d_in[5];
    const float* b_qkv  = (const float*)d_in[6];
    const float* w_proj = (const float*)d_in[7];
    const float* b_proj = (const float*)d_in[8];
    const float* g2     = (const float*)d_in[9];
    const float* b2     = (const float*)d_in[10];
    const float* w_fc1  = (const float*)d_in[11];
    const float* b_fc1  = (const float*)d_in[12];
    const float* w_fc2  = (const float*)d_in[13];
    const float* b_fc2  = (const float*)d_in[14];
    float* out = (float*)d_out;

    float *ln, *qkv, *attn, *x2, *fc1;
    cudaGetSymbolAddress((void**)&ln,   g_ln);
    cudaGetSymbolAddress((void**)&qkv,  g_qkv);
    cudaGetSymbolAddress((void**)&attn, g_attn);
    cudaGetSymbolAddress((void**)&x2,   g_x2);
    cudaGetSymbolAddress((void**)&fc1,  g_fc1);

    // 1) LN1
    ln_kernel<<<T_TOKENS / 8, 256>>>(x, g1, b1, ln);
    // 2) QKV projection
    gemm_kernel<0><<<dim3(QKV_DIM / 128, T_TOKENS / 128), 256>>>(
        ln, w_qkv, b_qkv, nullptr, qkv, T_TOKENS, QKV_DIM, C_DIM);
    // 3) window attention
    attn_kernel<<<2048 * HEADS, 64>>>(qkv, attn);
    // 4) proj + residual -> x2
    gemm_kernel<1><<<dim3(C_DIM / 128, T_TOKENS / 128), 256>>>(
        attn, w_proj, b_proj, x, x2, T_TOKENS, C_DIM, C_DIM);
    // 5) LN2
    ln_kernel<<<T_TOKENS / 8, 256>>>(x2, g2, b2, ln);
    // 6) FC1 + GELU
    gemm_kernel<2><<<dim3(HID / 128, T_TOKENS / 128), 256>>>(
        ln, w_fc1, b_fc1, nullptr, fc1, T_TOKENS, HID, C_DIM);
    // 7) FC2 + residual -> out
    gemm_kernel<1><<<dim3(C_DIM / 128, T_TOKENS / 128), 256>>>(
        fc1, w_fc2, b_fc2, x2, out, T_TOKENS, C_DIM, HID);
}

// round 4
// speedup vs baseline: 1.9799x; 1.9799x over previous
#include <cuda_runtime.h>
#include <cuda_bf16.h>
#include <math.h>
#include <stdint.h>

// ---------------- problem constants ----------------
#define T_TOKENS 100352      // 8 * 112 * 112
#define C_DIM    256
#define HID      1024
#define QKV_DIM  768
#define IMG      112
#define WS7      7
#define TOK_PER_IMG 12544

// weight element counts
#define W_QKV_ELEMS  (QKV_DIM * C_DIM)
#define W_PROJ_ELEMS (C_DIM * C_DIM)
#define W_FC1_ELEMS  (HID * C_DIM)
#define W_FC2_ELEMS  (C_DIM * HID)
#define W_TOTAL (W_QKV_ELEMS + W_PROJ_ELEMS + W_FC1_ELEMS + W_FC2_ELEMS)

// ---------------- scratch ----------------
__device__ __align__(16) __nv_bfloat16 g_ahi[(size_t)T_TOKENS * C_DIM];
__device__ __align__(16) __nv_bfloat16 g_alo[(size_t)T_TOKENS * C_DIM];
__device__ __align__(16) __nv_bfloat16 g_bhi[(size_t)T_TOKENS * HID];
__device__ __align__(16) __nv_bfloat16 g_blo[(size_t)T_TOKENS * HID];
__device__ __align__(16) __nv_bfloat16 g_whi[(size_t)W_TOTAL];
__device__ __align__(16) __nv_bfloat16 g_wlo[(size_t)W_TOTAL];
__device__ __align__(16) float g_qkv[(size_t)T_TOKENS * QKV_DIM];
__device__ __align__(16) float g_x2 [(size_t)T_TOKENS * C_DIM];

// ---------------- helpers ----------------
__device__ __forceinline__ uint32_t smem_u32(const void* p) {
    uint32_t a;
    asm("{ .reg .u64 t; cvta.to.shared.u64 t, %1; cvt.u32.u64 %0, t; }"
        : "=r"(a) : "l"(p));
    return a;
}
__device__ __forceinline__ uint32_t bf2_hi(float a, float b) {
    __nv_bfloat162 t = __floats2bfloat162_rn(a, b);
    return *reinterpret_cast<uint32_t*>(&t);
}
__device__ __forceinline__ uint32_t bf2_lo(float a, float b) {
    float ra = a - __bfloat162float(__float2bfloat16(a));
    float rb = b - __bfloat162float(__float2bfloat16(b));
    __nv_bfloat162 t = __floats2bfloat162_rn(ra, rb);
    return *reinterpret_cast<uint32_t*>(&t);
}
__device__ __forceinline__ void cp16(uint32_t dst, const void* src) {
    asm volatile("cp.async.ca.shared.global [%0], [%1], 16;"
                 :: "r"(dst), "l"(src) : "memory");
}
__device__ __forceinline__ void cp_commit() {
    asm volatile("cp.async.commit_group;" ::: "memory");
}
__device__ __forceinline__ void cp_wait1() {
    asm volatile("cp.async.wait_group 1;" ::: "memory");
}
#define LDM4(r, addr) \
    asm volatile("ldmatrix.sync.aligned.m8n8.x4.shared.b16 {%0,%1,%2,%3}, [%4];" \
        : "=r"((r)[0]), "=r"((r)[1]), "=r"((r)[2]), "=r"((r)[3]) : "r"(addr))
#define MMA(d, a, b) \
    asm volatile("mma.sync.aligned.m16n8k16.row.col.f32.bf16.bf16.f32 " \
        "{%0,%1,%2,%3}, {%4,%5,%6,%7}, {%8,%9}, {%0,%1,%2,%3};" \
        : "+f"((d)[0]), "+f"((d)[1]), "+f"((d)[2]), "+f"((d)[3]) \
        : "r"((a)[0]), "r"((a)[1]), "r"((a)[2]), "r"((a)[3]), \
          "r"((b)[0]), "r"((b)[1]))

// ---------------- weight split fp32 -> bf16 hi/lo ----------------
__global__ void wsplit_kernel(const float* __restrict__ w,
                              __nv_bfloat16* __restrict__ hi,
                              __nv_bfloat16* __restrict__ lo, int n) {
    int i = (blockIdx.x * 256 + threadIdx.x) * 4;
    if (i >= n) return;
    float4 v = *(const float4*)(w + i);
    *(uint2*)(hi + i) = make_uint2(bf2_hi(v.x, v.y), bf2_hi(v.z, v.w));
    *(uint2*)(lo + i) = make_uint2(bf2_lo(v.x, v.y), bf2_lo(v.z, v.w));
}

// ---------------- LayerNorm -> bf16 hi/lo ----------------
__global__ void ln_bf16_kernel(const float* __restrict__ x,
                               const float* __restrict__ gamma,
                               const float* __restrict__ beta,
                               __nv_bfloat16* __restrict__ ohi,
                               __nv_bfloat16* __restrict__ olo) {
    int row  = blockIdx.x * 8 + (threadIdx.x >> 5);
    int lane = threadIdx.x & 31;
    const float4* xr = (const float4*)(x + (size_t)row * C_DIM);
    float4 v0 = xr[lane];
    float4 v1 = xr[lane + 32];
    float s  = v0.x + v0.y + v0.z + v0.w + v1.x + v1.y + v1.z + v1.w;
    float s2 = v0.x*v0.x + v0.y*v0.y + v0.z*v0.z + v0.w*v0.w
             + v1.x*v1.x + v1.y*v1.y + v1.z*v1.z + v1.w*v1.w;
    #pragma unroll
    for (int o = 16; o > 0; o >>= 1) {
        s  += __shfl_xor_sync(0xffffffffu, s,  o);
        s2 += __shfl_xor_sync(0xffffffffu, s2, o);
    }
    float mean = s * (1.f / 256.f);
    float var  = s2 * (1.f / 256.f) - mean * mean;
    float inv  = rsqrtf(var + 1e-5f);

    const float4* gr = (const float4*)gamma;
    const float4* br = (const float4*)beta;
    float4 g0 = gr[lane], g1v = gr[lane + 32];
    float4 b0 = br[lane], b1v = br[lane + 32];
    float o0[4], o1[4];
    o0[0] = (v0.x - mean) * inv * g0.x + b0.x;
    o0[1] = (v0.y - mean) * inv * g0.y + b0.y;
    o0[2] = (v0.z - mean) * inv * g0.z + b0.z;
    o0[3] = (v0.w - mean) * inv * g0.w + b0.w;
    o1[0] = (v1.x - mean) * inv * g1v.x + b1v.x;
    o1[1] = (v1.y - mean) * inv * g1v.y + b1v.y;
    o1[2] = (v1.z - mean) * inv * g1v.z + b1v.z;
    o1[3] = (v1.w - mean) * inv * g1v.w + b1v.w;

    size_t base = (size_t)row * C_DIM;
    *(uint2*)(ohi + base + lane * 4)       = make_uint2(bf2_hi(o0[0], o0[1]), bf2_hi(o0[2], o0[3]));
    *(uint2*)(ohi + base + 128 + lane * 4) = make_uint2(bf2_hi(o1[0], o1[1]), bf2_hi(o1[2], o1[3]));
    *(uint2*)(olo + base + lane * 4)       = make_uint2(bf2_lo(o0[0], o0[1]), bf2_lo(o0[2], o0[3]));
    *(uint2*)(olo + base + 128 + lane * 4) = make_uint2(bf2_lo(o1[0], o1[1]), bf2_lo(o1[2], o1[3]));
}

// ---------------- mma.sync GEMM: C[M,N] = A[M,K] @ W[N,K]^T ----------------
// 128x128 CTA tile, BK=32, 3-stage cp.async pipeline, 8 warps (4m x 2n),
// warp tile 32x64, mma m16n8k16 bf16, 3-pass hi/lo split.
// smem per stage: Ah, Al, Wh, Wl, each 128 rows x 80B = 10240B -> 40960B.
// EPI: 0 = bias -> fp32; 1 = bias + residual -> fp32; 2 = bias + GELU -> bf16 hi/lo
#define STG_BYTES 40960
#define ARR_BYTES 10240
#define GEMM_SMEM (3 * STG_BYTES)

template<int EPI>
__global__ __launch_bounds__(256)
void gemm_mma(const __nv_bfloat16* __restrict__ Ahi,
              const __nv_bfloat16* __restrict__ Alo,
              const __nv_bfloat16* __restrict__ Whi,
              const __nv_bfloat16* __restrict__ Wlo,
              const float* __restrict__ bias,
              const float* __restrict__ res,
              float* __restrict__ outf,
              __nv_bfloat16* __restrict__ outhi,
              __nv_bfloat16* __restrict__ outlo,
              int N, int K) {
    extern __shared__ char smem[];
    uint32_t sb = smem_u32(smem);
    int tid  = threadIdx.x;
    int lane = tid & 31, w = tid >> 5;
    int wm = w >> 1, wn = w & 1;
    int m0 = blockIdx.y * 128, n0 = blockIdx.x * 128;
    const int NCH = K >> 5;

    // load thread mapping (2048 16B chunks per k-chunk, 8 per thread)
    // idx -> arr(0=Ah,1=Al,2=Wh,3=Wl), r (0-127), c (0-3)
    const __nv_bfloat16* srcs[4] = {Ahi, Alo, Whi, Wlo};

    float acc[2][8][4];
    #pragma unroll
    for (int mt = 0; mt < 2; mt++)
        #pragma unroll
        for (int nt = 0; nt < 8; nt++)
            #pragma unroll
            for (int q = 0; q < 4; q++) acc[mt][nt][q] = 0.f;

    // ---- issue helper (inlined twice) ----
    #define ISSUE_CHUNK(ch) do {                                               \
        int k0i = (ch) << 5;                                                   \
        uint32_t stb = sb + ((ch) % 3) * STG_BYTES;                            \
        _Pragma("unroll")                                                      \
        for (int i = 0; i < 8; i++) {                                          \
            int idx = i * 256 + tid;                                           \
            int arr = idx >> 9;                                                \
            int rem = idx & 511;                                               \
            int r = rem >> 2, c = rem & 3;                                     \
            int rb = (arr < 2) ? m0 : n0;                                      \
            const __nv_bfloat16* s = srcs[arr] + (size_t)(rb + r) * K + k0i + c * 8; \
            cp16(stb + arr * ARR_BYTES + r * 80 + c * 16, s);                  \
        }                                                                      \
        cp_commit();                                                           \
    } while (0)

    ISSUE_CHUNK(0);
    ISSUE_CHUNK(1);

    for (int ch = 0; ch < NCH; ch++) {
        cp_wait1();
        __syncthreads();
        if (ch + 2 < NCH) ISSUE_CHUNK(ch + 2);

        uint32_t As = sb + (ch % 3) * STG_BYTES;
        uint32_t Ws = As + 2 * ARR_BYTES;

        #pragma unroll
        for (int kk = 0; kk < 2; kk++) {
            uint32_t ah[2][4], al[2][4];
            {
                int arow = wm * 32 + (lane & 15);
                uint32_t akb = kk * 32 + ((lane & 16) ? 16u : 0u);
                #pragma unroll
                for (int mt = 0; mt < 2; mt++) {
                    uint32_t ad = As + (uint32_t)(arow + mt * 16) * 80 + akb;
                    LDM4(ah[mt], ad);
                    LDM4(al[mt], ad + ARR_BYTES);
                }
            }
            uint32_t bh[8][2], bl[8][2];
            {
                int brow = wn * 64 + (lane & 7) + ((lane & 16) ? 8 : 0);
                uint32_t bkb = kk * 32 + ((lane & 8) ? 16u : 0u);
                #pragma unroll
                for (int p = 0; p < 4; p++) {
                    uint32_t bd = Ws + (uint32_t)(brow + p * 16) * 80 + bkb;
                    uint32_t t[4];
                    LDM4(t, bd);
                    bh[2*p][0] = t[0]; bh[2*p][1] = t[1];
                    bh[2*p+1][0] = t[2]; bh[2*p+1][1] = t[3];
                    LDM4(t, bd + ARR_BYTES);
                    bl[2*p][0] = t[0]; bl[2*p][1] = t[1];
                    bl[2*p+1][0] = t[2]; bl[2*p+1][1] = t[3];
                }
            }
            #pragma unroll
            for (int mt = 0; mt < 2; mt++)
                #pragma unroll
                for (int nt = 0; nt < 8; nt++) {
                    MMA(acc[mt][nt], ah[mt], bh[nt]);
                    MMA(acc[mt][nt], ah[mt], bl[nt]);
                    MMA(acc[mt][nt], al[mt], bh[nt]);
                }
        }
        __syncthreads();
    }

    // ---- epilogue: registers -> global ----
    int lg = lane >> 2, lt = lane & 3;
    #pragma unroll
    for (int mt = 0; mt < 2; mt++) {
        #pragma unroll
        for (int h = 0; h < 2; h++) {
            size_t m = (size_t)(m0 + wm * 32 + mt * 16 + lg + h * 8);
            #pragma unroll
            for (int nt = 0; nt < 8; nt++) {
                int n = n0 + wn * 64 + nt * 8 + lt * 2;
                float2 bv = *(const float2*)(bias + n);
                float v0 = acc[mt][nt][h * 2 + 0] + bv.x;
                float v1 = acc[mt][nt][h * 2 + 1] + bv.y;
                if (EPI == 0) {
                    *(float2*)(outf + m * N + n) = make_float2(v0, v1);
                } else if (EPI == 1) {
                    float2 rr = *(const float2*)(res + m * N + n);
                    *(float2*)(outf + m * N + n) = make_float2(v0 + rr.x, v1 + rr.y);
                } else {
                    v0 = 0.5f * v0 * (1.f + erff(v0 * 0.7071067811865476f));
                    v1 = 0.5f * v1 * (1.f + erff(v1 * 0.7071067811865476f));
                    *(uint32_t*)(outhi + m * N + n) = bf2_hi(v0, v1);
                    *(uint32_t*)(outlo + m * N + n) = bf2_lo(v0, v1);
                }
            }
        }
    }
    #undef ISSUE_CHUNK
}

// ---------------- fused window attention -> bf16 hi/lo ----------------
__global__ void attn_kernel(const float* __restrict__ qkv,
                            __nv_bfloat16* __restrict__ ohi,
                            __nv_bfloat16* __restrict__ olo) {
    __shared__ float ks[49][32];
    __shared__ float vs[49][32];
    __shared__ float ss[49][56];
    __shared__ int   tok[49];

    int head = blockIdx.x & 7;
    int win  = blockIdx.x >> 3;
    int n    = win >> 8;
    int wrem = win & 255;
    int wr   = wrem >> 4;
    int wc   = wrem & 15;
    int tid  = threadIdx.x;

    if (tid < 49) {
        int hh = wr * WS7 + tid / 7;
        int ww = wc * WS7 + tid % 7;
        tok[tid] = n * TOK_PER_IMG + hh * IMG + ww;
    }
    __syncthreads();

    int cb = head * 32;
    for (int i = tid; i < 49 * 8; i += 64) {
        int rowi = i >> 3;
        int c4   = (i & 7) * 4;
        const float* base = qkv + (size_t)tok[rowi] * QKV_DIM;
        *(float4*)&ks[rowi][c4] = *(const float4*)(base + C_DIM     + cb + c4);
        *(float4*)&vs[rowi][c4] = *(const float4*)(base + 2 * C_DIM + cb + c4);
    }
    __syncthreads();

    if (tid < 49) {
        float qr[32];
        const float* qb = qkv + (size_t)tok[tid] * QKV_DIM + cb;
        #pragma unroll
        for (int dd = 0; dd < 32; dd += 4) {
            float4 v = *(const float4*)(qb + dd);
            qr[dd] = v.x; qr[dd + 1] = v.y; qr[dd + 2] = v.z; qr[dd + 3] = v.w;
        }
        const float scale = 0.17677669529663687f;
        float mx = -1e30f;
        for (int m = 0; m < 49; m++) {
            float d = 0.f;
            #pragma unroll
            for (int dd = 0; dd < 32; dd++) d += qr[dd] * ks[m][dd];
            d *= scale;
            ss[tid][m] = d;
            mx = fmaxf(mx, d);
        }
        float sum = 0.f;
        for (int m = 0; m < 49; m++) {
            float e = __expf(ss[tid][m] - mx);
            ss[tid][m] = e;
            sum += e;
        }
        float inv = 1.f / sum;
        float out[32];
        #pragma unroll
        for (int dd = 0; dd < 32; dd++) out[dd] = 0.f;
        for (int m = 0; m < 49; m++) {
            float p = ss[tid][m];
            #pragma unroll
            for (int dd = 0; dd < 32; dd++) out[dd] += p * vs[m][dd];
        }
        size_t ob = (size_t)tok[tid] * C_DIM + cb;
        #pragma unroll
        for (int dd = 0; dd < 32; dd += 4) {
            float t0 = out[dd] * inv, t1 = out[dd + 1] * inv;
            float t2 = out[dd + 2] * inv, t3 = out[dd + 3] * inv;
            *(uint2*)(ohi + ob + dd) = make_uint2(bf2_hi(t0, t1), bf2_hi(t2, t3));
            *(uint2*)(olo + ob + dd) = make_uint2(bf2_lo(t0, t1), bf2_lo(t2, t3));
        }
    }
}

// ---------------- launch ----------------
extern "C" void kernel_launch(void* const* d_in, const int* in_sizes, int n_in,
                              void* d_out, int out_size) {
    const float* x      = (const float*)d_in[0];
    const float* g1     = (const float*)d_in[3];
    const float* b1     = (const float*)d_in[4];
    const float* w_qkv  = (const float*)d_in[5];
    const float* b_qkv  = (const float*)d_in[6];
    const float* w_proj = (const float*)d_in[7];
    const float* b_proj = (const float*)d_in[8];
    const float* g2     = (const float*)d_in[9];
    const float* b2     = (const float*)d_in[10];
    const float* w_fc1  = (const float*)d_in[11];
    const float* b_fc1  = (const float*)d_in[12];
    const float* w_fc2  = (const float*)d_in[13];
    const float* b_fc2  = (const float*)d_in[14];
    float* out = (float*)d_out;

    __nv_bfloat16 *ahi, *alo, *bhi, *blo, *whi, *wlo;
    float *qkv, *x2;
    cudaGetSymbolAddress((void**)&ahi, g_ahi);
    cudaGetSymbolAddress((void**)&alo, g_alo);
    cudaGetSymbolAddress((void**)&bhi, g_bhi);
    cudaGetSymbolAddress((void**)&blo, g_blo);
    cudaGetSymbolAddress((void**)&whi, g_whi);
    cudaGetSymbolAddress((void**)&wlo, g_wlo);
    cudaGetSymbolAddress((void**)&qkv, g_qkv);
    cudaGetSymbolAddress((void**)&x2,  g_x2);

    // weight split offsets
    __nv_bfloat16* wqkv_hi = whi;
    __nv_bfloat16* wqkv_lo = wlo;
    __nv_bfloat16* wproj_hi = whi + W_QKV_ELEMS;
    __nv_bfloat16* wproj_lo = wlo + W_QKV_ELEMS;
    __nv_bfloat16* wfc1_hi = wproj_hi + W_PROJ_ELEMS;
    __nv_bfloat16* wfc1_lo = wproj_lo + W_PROJ_ELEMS;
    __nv_bfloat16* wfc2_hi = wfc1_hi + W_FC1_ELEMS;
    __nv_bfloat16* wfc2_lo = wfc1_lo + W_FC1_ELEMS;

    cudaFuncSetAttribute(gemm_mma<0>, cudaFuncAttributeMaxDynamicSharedMemorySize, GEMM_SMEM);
    cudaFuncSetAttribute(gemm_mma<1>, cudaFuncAttributeMaxDynamicSharedMemorySize, GEMM_SMEM);
    cudaFuncSetAttribute(gemm_mma<2>, cudaFuncAttributeMaxDynamicSharedMemorySize, GEMM_SMEM);

    const int MT = T_TOKENS / 128;  // 784

    // 0) split weights to bf16 hi/lo
    wsplit_kernel<<<W_QKV_ELEMS  / 1024, 256>>>(w_qkv,  wqkv_hi,  wqkv_lo,  W_QKV_ELEMS);
    wsplit_kernel<<<W_PROJ_ELEMS / 1024, 256>>>(w_proj, wproj_hi, wproj_lo, W_PROJ_ELEMS);
    wsplit_kernel<<<W_FC1_ELEMS  / 1024, 256>>>(w_fc1,  wfc1_hi,  wfc1_lo,  W_FC1_ELEMS);
    wsplit_kernel<<<W_FC2_ELEMS  / 1024, 256>>>(w_fc2,  wfc2_hi,  wfc2_lo,  W_FC2_ELEMS);

    // 1) LN1 -> bf16 hi/lo
    ln_bf16_kernel<<<T_TOKENS / 8, 256>>>(x, g1, b1, ahi, alo);
    // 2) QKV projection (fp32 out)
    gemm_mma<0><<<dim3(QKV_DIM / 128, MT), 256, GEMM_SMEM>>>(
        ahi, alo, wqkv_hi, wqkv_lo, b_qkv, nullptr, qkv, nullptr, nullptr, QKV_DIM, C_DIM);
    // 3) window attention -> bf16 hi/lo
    attn_kernel<<<2048 * 8, 64>>>(qkv, ahi, alo);
    // 4) proj + residual(x) -> x2
    gemm_mma<1><<<dim3(C_DIM / 128, MT), 256, GEMM_SMEM>>>(
        ahi, alo, wproj_hi, wproj_lo, b_proj, x, x2, nullptr, nullptr, C_DIM, C_DIM);
    // 5) LN2 -> bf16 hi/lo
    ln_bf16_kernel<<<T_TOKENS / 8, 256>>>(x2, g2, b2, ahi, alo);
    // 6) FC1 + GELU -> bf16 hi/lo
    gemm_mma<2><<<dim3(HID / 128, MT), 256, GEMM_SMEM>>>(
        ahi, alo, wfc1_hi, wfc1_lo, b_fc1, nullptr, nullptr, bhi, blo, HID, C_DIM);
    // 7) FC2 + residual(x2) -> out
    gemm_mma<1><<<dim3(C_DIM / 128, MT), 256, GEMM_SMEM>>>(
        bhi, blo, wfc2_hi, wfc2_lo, b_fc2, x2, out, nullptr, nullptr, C_DIM, HID);
}

// round 5
// speedup vs baseline: 4.0422x; 2.0416x over previous
#include <cuda_runtime.h>
#include <cuda_fp16.h>
#include <math.h>
#include <stdint.h>

// ---------------- problem constants ----------------
#define T_TOKENS 100352      // 8 * 112 * 112
#define C_DIM    256
#define HID      1024
#define QKV_DIM  768
#define IMG      112
#define WS7      7
#define TOK_PER_IMG 12544

#define W_QKV_ELEMS  (QKV_DIM * C_DIM)
#define W_PROJ_ELEMS (C_DIM * C_DIM)
#define W_FC1_ELEMS  (HID * C_DIM)
#define W_FC2_ELEMS  (C_DIM * HID)
#define W_TOTAL (W_QKV_ELEMS + W_PROJ_ELEMS + W_FC1_ELEMS + W_FC2_ELEMS)

// ---------------- scratch ----------------
__device__ __align__(16) __half g_a  [(size_t)T_TOKENS * C_DIM];
__device__ __align__(16) __half g_b  [(size_t)T_TOKENS * HID];
__device__ __align__(16) __half g_w  [(size_t)W_TOTAL];
__device__ __align__(16) float  g_qkv[(size_t)T_TOKENS * QKV_DIM];
__device__ __align__(16) float  g_x2 [(size_t)T_TOKENS * C_DIM];

// ---------------- helpers ----------------
__device__ __forceinline__ uint32_t smem_u32(const void* p) {
    uint32_t a;
    asm("{ .reg .u64 t; cvta.to.shared.u64 t, %1; cvt.u32.u64 %0, t; }"
        : "=r"(a) : "l"(p));
    return a;
}
__device__ __forceinline__ uint32_t h2pack(float a, float b) {
    __half2 t = __floats2half2_rn(a, b);
    return *reinterpret_cast<uint32_t*>(&t);
}
__device__ __forceinline__ void cp16(uint32_t dst, const void* src) {
    asm volatile("cp.async.cg.shared.global [%0], [%1], 16;"
                 :: "r"(dst), "l"(src) : "memory");
}
__device__ __forceinline__ void cp_commit() {
    asm volatile("cp.async.commit_group;" ::: "memory");
}
__device__ __forceinline__ void cp_wait1() {
    asm volatile("cp.async.wait_group 1;" ::: "memory");
}
#define LDM4(r, addr) \
    asm volatile("ldmatrix.sync.aligned.m8n8.x4.shared.b16 {%0,%1,%2,%3}, [%4];" \
        : "=r"((r)[0]), "=r"((r)[1]), "=r"((r)[2]), "=r"((r)[3]) : "r"(addr))
#define MMA(d, a, b) \
    asm volatile("mma.sync.aligned.m16n8k16.row.col.f32.f16.f16.f32 " \
        "{%0,%1,%2,%3}, {%4,%5,%6,%7}, {%8,%9}, {%0,%1,%2,%3};" \
        : "+f"((d)[0]), "+f"((d)[1]), "+f"((d)[2]), "+f"((d)[3]) \
        : "r"((a)[0]), "r"((a)[1]), "r"((a)[2]), "r"((a)[3]), \
          "r"((b)[0]), "r"((b)[1]))

// ---------------- weight convert fp32 -> fp16 ----------------
__global__ void wconv_kernel(const float* __restrict__ w,
                             __half* __restrict__ h, int n) {
    int i = (blockIdx.x * 256 + threadIdx.x) * 4;
    if (i >= n) return;
    float4 v = *(const float4*)(w + i);
    *(uint2*)(h + i) = make_uint2(h2pack(v.x, v.y), h2pack(v.z, v.w));
}

// ---------------- LayerNorm -> fp16 ----------------
__global__ void ln_h_kernel(const float* __restrict__ x,
                            const float* __restrict__ gamma,
                            const float* __restrict__ beta,
                            __half* __restrict__ oh) {
    int row  = blockIdx.x * 8 + (threadIdx.x >> 5);
    int lane = threadIdx.x & 31;
    const float4* xr = (const float4*)(x + (size_t)row * C_DIM);
    float4 v0 = xr[lane];
    float4 v1 = xr[lane + 32];
    float s  = v0.x + v0.y + v0.z + v0.w + v1.x + v1.y + v1.z + v1.w;
    float s2 = v0.x*v0.x + v0.y*v0.y + v0.z*v0.z + v0.w*v0.w
             + v1.x*v1.x + v1.y*v1.y + v1.z*v1.z + v1.w*v1.w;
    #pragma unroll
    for (int o = 16; o > 0; o >>= 1) {
        s  += __shfl_xor_sync(0xffffffffu, s,  o);
        s2 += __shfl_xor_sync(0xffffffffu, s2, o);
    }
    float mean = s * (1.f / 256.f);
    float var  = s2 * (1.f / 256.f) - mean * mean;
    float inv  = rsqrtf(var + 1e-5f);

    const float4* gr = (const float4*)gamma;
    const float4* br = (const float4*)beta;
    float4 g0 = gr[lane], g1v = gr[lane + 32];
    float4 b0 = br[lane], b1v = br[lane + 32];
    float o0[4], o1[4];
    o0[0] = (v0.x - mean) * inv * g0.x + b0.x;
    o0[1] = (v0.y - mean) * inv * g0.y + b0.y;
    o0[2] = (v0.z - mean) * inv * g0.z + b0.z;
    o0[3] = (v0.w - mean) * inv * g0.w + b0.w;
    o1[0] = (v1.x - mean) * inv * g1v.x + b1v.x;
    o1[1] = (v1.y - mean) * inv * g1v.y + b1v.y;
    o1[2] = (v1.z - mean) * inv * g1v.z + b1v.z;
    o1[3] = (v1.w - mean) * inv * g1v.w + b1v.w;

    size_t base = (size_t)row * C_DIM;
    *(uint2*)(oh + base + lane * 4)       = make_uint2(h2pack(o0[0], o0[1]), h2pack(o0[2], o0[3]));
    *(uint2*)(oh + base + 128 + lane * 4) = make_uint2(h2pack(o1[0], o1[1]), h2pack(o1[2], o1[3]));
}

// ---------------- mma.sync GEMM: C[M,N] = A[M,K] @ W[N,K]^T ----------------
// 128x128 CTA tile, BK=64, 3-stage cp.async pipeline, 8 warps (4m x 2n),
// warp tile 32x64, single-pass fp16 mma m16n8k16.
// smem per stage: A, W each 128 rows x 144B = 18432B -> 36864B per stage.
// EPI: 0 = bias -> fp32; 1 = bias + residual -> fp32; 2 = bias + GELU -> fp16
#define ARR_BYTES 18432
#define STG_BYTES 36864
#define GEMM_SMEM (3 * STG_BYTES)

template<int EPI>
__global__ __launch_bounds__(256)
void gemm_mma(const __half* __restrict__ A,
              const __half* __restrict__ W,
              const float* __restrict__ bias,
              const float* __restrict__ res,
              float* __restrict__ outf,
              __half* __restrict__ outh,
              int N, int K) {
    extern __shared__ char smem[];
    uint32_t sb = smem_u32(smem);
    int tid  = threadIdx.x;
    int lane = tid & 31, w = tid >> 5;
    int wm = w >> 1, wn = w & 1;
    int m0 = blockIdx.y * 128, n0 = blockIdx.x * 128;
    const int NCH = K >> 6;

    float acc[2][8][4];
    #pragma unroll
    for (int mt = 0; mt < 2; mt++)
        #pragma unroll
        for (int nt = 0; nt < 8; nt++)
            #pragma unroll
            for (int q = 0; q < 4; q++) acc[mt][nt][q] = 0.f;

    // per chunk: A 128x64 fp16 (16KB = 1024 chunks of 16B) + W same -> 2048 chunks, 8/thread
    #define ISSUE_CHUNK(ch) do {                                               \
        int k0i = (ch) << 6;                                                   \
        uint32_t stb = sb + ((ch) % 3) * STG_BYTES;                            \
        _Pragma("unroll")                                                      \
        for (int i = 0; i < 8; i++) {                                          \
            int idx = i * 256 + tid;                                           \
            int arr = idx >> 10;                                               \
            int rem = idx & 1023;                                              \
            int r = rem >> 3, c = rem & 7;                                     \
            const __half* s = (arr ? W + (size_t)(n0 + r) * K                  \
                                   : A + (size_t)(m0 + r) * K) + k0i + c * 8;  \
            cp16(stb + arr * ARR_BYTES + r * 144 + c * 16, s);                 \
        }                                                                      \
        cp_commit();                                                           \
    } while (0)

    ISSUE_CHUNK(0);
    ISSUE_CHUNK(1);

    for (int ch = 0; ch < NCH; ch++) {
        cp_wait1();
        __syncthreads();
        if (ch + 2 < NCH) ISSUE_CHUNK(ch + 2);
        else cp_commit();   // keep group accounting aligned so wait1 bounds chunk ch

        uint32_t As = sb + (ch % 3) * STG_BYTES;
        uint32_t Ws = As + ARR_BYTES;

        #pragma unroll
        for (int kk = 0; kk < 4; kk++) {
            uint32_t ah[2][4];
            {
                int arow = wm * 32 + (lane & 15);
                uint32_t akb = kk * 32 + ((lane & 16) ? 16u : 0u);
                #pragma unroll
                for (int mt = 0; mt < 2; mt++)
                    LDM4(ah[mt], As + (uint32_t)(arow + mt * 16) * 144 + akb);
            }
            uint32_t bh[8][2];
            {
                int brow = wn * 64 + (lane & 7) + ((lane & 16) ? 8 : 0);
                uint32_t bkb = kk * 32 + ((lane & 8) ? 16u : 0u);
                #pragma unroll
                for (int p = 0; p < 4; p++) {
                    uint32_t t[4];
                    LDM4(t, Ws + (uint32_t)(brow + p * 16) * 144 + bkb);
                    bh[2*p][0] = t[0]; bh[2*p][1] = t[1];
                    bh[2*p+1][0] = t[2]; bh[2*p+1][1] = t[3];
                }
            }
            #pragma unroll
            for (int mt = 0; mt < 2; mt++)
                #pragma unroll
                for (int nt = 0; nt < 8; nt++)
                    MMA(acc[mt][nt], ah[mt], bh[nt]);
        }
    }

    // ---- epilogue: registers -> global ----
    int lg = lane >> 2, lt = lane & 3;
    #pragma unroll
    for (int mt = 0; mt < 2; mt++) {
        #pragma unroll
        for (int h = 0; h < 2; h++) {
            size_t m = (size_t)(m0 + wm * 32 + mt * 16 + lg + h * 8);
            #pragma unroll
            for (int nt = 0; nt < 8; nt++) {
                int n = n0 + wn * 64 + nt * 8 + lt * 2;
                float2 bv = *(const float2*)(bias + n);
                float v0 = acc[mt][nt][h * 2 + 0] + bv.x;
                float v1 = acc[mt][nt][h * 2 + 1] + bv.y;
                if (EPI == 0) {
                    *(float2*)(outf + m * N + n) = make_float2(v0, v1);
                } else if (EPI == 1) {
                    float2 rr = *(const float2*)(res + m * N + n);
                    *(float2*)(outf + m * N + n) = make_float2(v0 + rr.x, v1 + rr.y);
                } else {
                    v0 = 0.5f * v0 * (1.f + erff(v0 * 0.7071067811865476f));
                    v1 = 0.5f * v1 * (1.f + erff(v1 * 0.7071067811865476f));
                    *(uint32_t*)(outh + m * N + n) = h2pack(v0, v1);
                }
            }
        }
    }
    #undef ISSUE_CHUNK
}

// ---------------- fused window attention -> fp16 ----------------
__global__ void attn_kernel(const float* __restrict__ qkv,
                            __half* __restrict__ oh) {
    __shared__ float ks[49][32];
    __shared__ float vs[49][32];
    __shared__ float ss[49][56];
    __shared__ int   tok[49];

    int head = blockIdx.x & 7;
    int win  = blockIdx.x >> 3;
    int n    = win >> 8;
    int wrem = win & 255;
    int wr   = wrem >> 4;
    int wc   = wrem & 15;
    int tid  = threadIdx.x;

    if (tid < 49) {
        int hh = wr * WS7 + tid / 7;
        int ww = wc * WS7 + tid % 7;
        tok[tid] = n * TOK_PER_IMG + hh * IMG + ww;
    }
    __syncthreads();

    int cb = head * 32;
    for (int i = tid; i < 49 * 8; i += 64) {
        int rowi = i >> 3;
        int c4   = (i & 7) * 4;
        const float* base = qkv + (size_t)tok[rowi] * QKV_DIM;
        *(float4*)&ks[rowi][c4] = *(const float4*)(base + C_DIM     + cb + c4);
        *(float4*)&vs[rowi][c4] = *(const float4*)(base + 2 * C_DIM + cb + c4);
    }
    __syncthreads();

    if (tid < 49) {
        float qr[32];
        const float* qb = qkv + (size_t)tok[tid] * QKV_DIM + cb;
        #pragma unroll
        for (int dd = 0; dd < 32; dd += 4) {
            float4 v = *(const float4*)(qb + dd);
            qr[dd] = v.x; qr[dd + 1] = v.y; qr[dd + 2] = v.z; qr[dd + 3] = v.w;
        }
        const float scale = 0.17677669529663687f;
        float mx = -1e30f;
        for (int m = 0; m < 49; m++) {
            float d = 0.f;
            #pragma unroll
            for (int dd = 0; dd < 32; dd++) d += qr[dd] * ks[m][dd];
            d *= scale;
            ss[tid][m] = d;
            mx = fmaxf(mx, d);
        }
        float sum = 0.f;
        for (int m = 0; m < 49; m++) {
            float e = __expf(ss[tid][m] - mx);
            ss[tid][m] = e;
            sum += e;
        }
        float inv = 1.f / sum;
        float out[32];
        #pragma unroll
        for (int dd = 0; dd < 32; dd++) out[dd] = 0.f;
        for (int m = 0; m < 49; m++) {
            float p = ss[tid][m];
            #pragma unroll
            for (int dd = 0; dd < 32; dd++) out[dd] += p * vs[m][dd];
        }
        size_t ob = (size_t)tok[tid] * C_DIM + cb;
        #pragma unroll
        for (int dd = 0; dd < 32; dd += 4) {
            *(uint2*)(oh + ob + dd) =
                make_uint2(h2pack(out[dd] * inv,     out[dd + 1] * inv),
                           h2pack(out[dd + 2] * inv, out[dd + 3] * inv));
        }
    }
}

// ---------------- launch ----------------
extern "C" void kernel_launch(void* const* d_in, const int* in_sizes, int n_in,
                              void* d_out, int out_size) {
    const float* x      = (const float*)d_in[0];
    const float* g1     = (const float*)d_in[3];
    const float* b1     = (const float*)d_in[4];
    const float* w_qkv  = (const float*)d_in[5];
    const float* b_qkv  = (const float*)d_in[6];
    const float* w_proj = (const float*)d_in[7];
    const float* b_proj = (const float*)d_in[8];
    const float* g2     = (const float*)d_in[9];
    const float* b2     = (const float*)d_in[10];
    const float* w_fc1  = (const float*)d_in[11];
    const float* b_fc1  = (const float*)d_in[12];
    const float* w_fc2  = (const float*)d_in[13];
    const float* b_fc2  = (const float*)d_in[14];
    float* out = (float*)d_out;

    __half *ah, *bh, *wh;
    float *qkv, *x2;
    cudaGetSymbolAddress((void**)&ah,  g_a);
    cudaGetSymbolAddress((void**)&bh,  g_b);
    cudaGetSymbolAddress((void**)&wh,  g_w);
    cudaGetSymbolAddress((void**)&qkv, g_qkv);
    cudaGetSymbolAddress((void**)&x2,  g_x2);

    __half* wqkv_h  = wh;
    __half* wproj_h = wqkv_h  + W_QKV_ELEMS;
    __half* wfc1_h  = wproj_h + W_PROJ_ELEMS;
    __half* wfc2_h  = wfc1_h  + W_FC1_ELEMS;

    cudaFuncSetAttribute(gemm_mma<0>, cudaFuncAttributeMaxDynamicSharedMemorySize, GEMM_SMEM);
    cudaFuncSetAttribute(gemm_mma<1>, cudaFuncAttributeMaxDynamicSharedMemorySize, GEMM_SMEM);
    cudaFuncSetAttribute(gemm_mma<2>, cudaFuncAttributeMaxDynamicSharedMemorySize, GEMM_SMEM);

    const int MT = T_TOKENS / 128;  // 784

    // 0) convert weights to fp16
    wconv_kernel<<<W_QKV_ELEMS  / 1024, 256>>>(w_qkv,  wqkv_h,  W_QKV_ELEMS);
    wconv_kernel<<<W_PROJ_ELEMS / 1024, 256>>>(w_proj, wproj_h, W_PROJ_ELEMS);
    wconv_kernel<<<W_FC1_ELEMS  / 1024, 256>>>(w_fc1,  wfc1_h,  W_FC1_ELEMS);
    wconv_kernel<<<W_FC2_ELEMS  / 1024, 256>>>(w_fc2,  wfc2_h,  W_FC2_ELEMS);

    // 1) LN1 -> fp16
    ln_h_kernel<<<T_TOKENS / 8, 256>>>(x, g1, b1, ah);
    // 2) QKV projection (fp32 out)
    gemm_mma<0><<<dim3(QKV_DIM / 128, MT), 256, GEMM_SMEM>>>(
        ah, wqkv_h, b_qkv, nullptr, qkv, nullptr, QKV_DIM, C_DIM);
    // 3) window attention -> fp16
    attn_kernel<<<2048 * 8, 64>>>(qkv, ah);
    // 4) proj + residual(x) -> x2
    gemm_mma<1><<<dim3(C_DIM / 128, MT), 256, GEMM_SMEM>>>(
        ah, wproj_h, b_proj, x, x2, nullptr, C_DIM, C_DIM);
    // 5) LN2 -> fp16
    ln_h_kernel<<<T_TOKENS / 8, 256>>>(x2, g2, b2, ah);
    // 6) FC1 + GELU -> fp16
    gemm_mma<2><<<dim3(HID / 128, MT), 256, GEMM_SMEM>>>(
        ah, wfc1_h, b_fc1, nullptr, nullptr, bh, HID, C_DIM);
    // 7) FC2 + residual(x2) -> out
    gemm_mma<1><<<dim3(C_DIM / 128, MT), 256, GEMM_SMEM>>>(
        bh, wfc2_h, b_fc2, x2, out, nullptr, C_DIM, HID);
}